// round 13
// baseline (speedup 1.0000x reference)
#include <cuda_runtime.h>
#include <math_constants.h>

// Problem: B=32, T=2048, D=512, fp32
//   energy[b,t]    = dot(key[b,t,:], query[b,:])
//   attention[b,t] = softmax_T(energy)[b,t]
//   out[b,d]       = sum_t attention[b,t] * value[b,t,d]
// d_out layout: out (32*512 floats) then attention (32*2048 floats)
//
// Split-softmax (exact): per 32-row chunk compute local m, p=exp(e-m), s=sum p,
// partial_out = sum p*V. Merge: M=max m, S=sum s*exp(m-M);
// attn = p*exp(m-M)/S, out = sum partial*exp(m-M)/S.

#define B 32
#define T 2048
#define D 512
#define CHUNK 32
#define NCHUNK (T / CHUNK)   // 64

// Scratch (no allocations allowed in kernel_launch)
__device__ float g_p[B * T];                    // exp(e - m_chunk)
__device__ float g_stats[B * NCHUNK * 2];       // (m, s) per chunk
__device__ float g_part[B * NCHUNK * D];        // per-chunk partial out (4MB)

// ---------------------------------------------------------------------------
// Kernel A: fused QK + local softmax + weighted V accumulation per chunk.
// Grid (NCHUNK, B) = 2048 blocks x 256 threads.
// ---------------------------------------------------------------------------
__global__ void __launch_bounds__(256) fused_kernel(
        const float* __restrict__ query,
        const float* __restrict__ key,
        const float* __restrict__ value,
        float* __restrict__ gp,
        float* __restrict__ stats,
        float* __restrict__ part) {
    int ts = blockIdx.x;        // chunk index 0..63
    int b  = blockIdx.y;        // batch
    int tid = threadIdx.x;      // 0..255
    int lane = tid & 31;
    int warp = tid >> 5;        // 0..7

    __shared__ float4 qs[D / 4];      // 2KB: q row for this batch
    __shared__ float es[CHUNK];       // raw energies
    __shared__ float ps[CHUNK];       // exp(e - m)
    __shared__ float4 vtmp[D / 4];    // half-combine buffer

    if (tid < D / 4)
        qs[tid] = ((const float4*)(query + (size_t)b * D))[tid];
    __syncthreads();

    int t0 = ts * CHUNK;

    // ---- QK phase: warp w -> local rows [4w, 4w+4), two 2-row iterations.
    // Front-batch 8 streaming k LDG.128 before any arithmetic; q from smem.
#pragma unroll
    for (int it = 0; it < 2; it++) {
        int r = warp * 4 + it * 2;
        const float4* k0 = (const float4*)(key + ((size_t)b * T + t0 + r) * D);

        float4 ka[4], kb[4];
#pragma unroll
        for (int i = 0; i < 4; i++) ka[i] = k0[lane + 32 * i];
#pragma unroll
        for (int i = 0; i < 4; i++) kb[i] = k0[128 + lane + 32 * i];

        float acc0 = 0.0f, acc1 = 0.0f;
#pragma unroll
        for (int i = 0; i < 4; i++) {
            float4 qv = qs[lane + 32 * i];
            acc0 += ka[i].x * qv.x + ka[i].y * qv.y +
                    ka[i].z * qv.z + ka[i].w * qv.w;
            acc1 += kb[i].x * qv.x + kb[i].y * qv.y +
                    kb[i].z * qv.z + kb[i].w * qv.w;
        }
#pragma unroll
        for (int off = 16; off; off >>= 1) {
            acc0 += __shfl_xor_sync(0xFFFFFFFFu, acc0, off);
            acc1 += __shfl_xor_sync(0xFFFFFFFFu, acc1, off);
        }
        if (lane == 0) {
            es[r]     = acc0;
            es[r + 1] = acc1;
        }
    }
    __syncthreads();

    // ---- Local softmax stats: warp 0 (32 values = CHUNK).
    if (warp == 0) {
        float e = es[lane];
        float m = e;
#pragma unroll
        for (int off = 16; off; off >>= 1)
            m = fmaxf(m, __shfl_xor_sync(0xFFFFFFFFu, m, off));
        float p = __expf(e - m);
        float s = p;
#pragma unroll
        for (int off = 16; off; off >>= 1)
            s += __shfl_xor_sync(0xFFFFFFFFu, s, off);
        ps[lane] = p;
        gp[(size_t)b * T + t0 + lane] = p;
        if (lane == 0) {
            stats[((size_t)b * NCHUNK + ts) * 2]     = m;
            stats[((size_t)b * NCHUNK + ts) * 2 + 1] = s;
        }
    }
    __syncthreads();

    // ---- V phase: thread owns float4 column c; halves h=0/1 cover 16 rows.
    int c = tid & 127;
    int h = tid >> 7;
    const float4* v0 = (const float4*)(value + ((size_t)b * T + t0 + h * 16) * D);
    float4 acc = make_float4(0.f, 0.f, 0.f, 0.f);
#pragma unroll 8
    for (int i = 0; i < 16; i++) {
        float a = ps[h * 16 + i];
        float4 vv = v0[(size_t)i * (D / 4) + c];
        acc.x += a * vv.x;
        acc.y += a * vv.y;
        acc.z += a * vv.z;
        acc.w += a * vv.w;
    }
    if (h == 1) vtmp[c] = acc;
    __syncthreads();
    if (h == 0) {
        float4 o = vtmp[c];
        acc.x += o.x; acc.y += o.y; acc.z += o.z; acc.w += o.w;
        ((float4*)part)[((size_t)b * NCHUNK + ts) * (D / 4) + c] = acc;
    }
}

// ---------------------------------------------------------------------------
// Kernel B: merge. One block per batch, 256 threads.
//   M = max m_ts ; S = sum s_ts*exp(m_ts-M) ; w_ts = exp(m_ts-M)/S
//   attn[t] = p[t]*w_{t/32} ; out[d] = sum_ts part[ts,d]*w_ts
// ---------------------------------------------------------------------------
__global__ void __launch_bounds__(256) merge_kernel(
        const float* __restrict__ gp,
        const float* __restrict__ stats,
        const float* __restrict__ part,
        float* __restrict__ out,
        float* __restrict__ attn) {
    int b = blockIdx.x;
    int tid = threadIdx.x;      // 0..255
    int lane = tid & 31;
    int warp = tid >> 5;

    __shared__ float w[NCHUNK];
    __shared__ float4 obuf[D / 4];

    if (warp == 0) {
        const float* st = stats + (size_t)b * NCHUNK * 2;
        float m0 = st[lane * 2],        s0 = st[lane * 2 + 1];
        float m1 = st[(lane + 32) * 2], s1 = st[(lane + 32) * 2 + 1];
        float M = fmaxf(m0, m1);
#pragma unroll
        for (int off = 16; off; off >>= 1)
            M = fmaxf(M, __shfl_xor_sync(0xFFFFFFFFu, M, off));
        float e0 = __expf(m0 - M), e1 = __expf(m1 - M);
        float s = s0 * e0 + s1 * e1;
#pragma unroll
        for (int off = 16; off; off >>= 1)
            s += __shfl_xor_sync(0xFFFFFFFFu, s, off);
        float invS = 1.0f / s;
        w[lane]      = e0 * invS;
        w[lane + 32] = e1 * invS;
    }
    __syncthreads();

    // attention: 2048 values, 8 per thread
    const float* gpb = gp + (size_t)b * T;
    float* ab = attn + (size_t)b * T;
#pragma unroll
    for (int i = 0; i < 8; i++) {
        int t = tid + 256 * i;
        ab[t] = gpb[t] * w[t >> 5];   // CHUNK = 32
    }

    // out: thread owns col c; halves split the 64 chunks
    int c = tid & 127;
    int h = tid >> 7;
    const float4* pb = (const float4*)part + (size_t)b * NCHUNK * (D / 4);
    float4 acc = make_float4(0.f, 0.f, 0.f, 0.f);
#pragma unroll 8
    for (int i = 0; i < 32; i++) {
        int ts = h * 32 + i;
        float4 p = pb[(size_t)ts * (D / 4) + c];
        float ww = w[ts];
        acc.x += ww * p.x;
        acc.y += ww * p.y;
        acc.z += ww * p.z;
        acc.w += ww * p.w;
    }
    if (h == 1) obuf[c] = acc;
    __syncthreads();
    if (h == 0) {
        float4 o = obuf[c];
        acc.x += o.x; acc.y += o.y; acc.z += o.z; acc.w += o.w;
        ((float4*)out)[(size_t)b * (D / 4) + c] = acc;
    }
}

extern "C" void kernel_launch(void* const* d_in, const int* in_sizes, int n_in,
                              void* d_out, int out_size) {
    const float* query = (const float*)d_in[0];  // [B, D]
    const float* key   = (const float*)d_in[1];  // [B, T, D]
    const float* value = (const float*)d_in[2];  // [B, T, D]

    float* out  = (float*)d_out;            // [B, D]
    float* attn = (float*)d_out + B * D;    // [B, T]

    float *gp, *stats, *part;
    cudaGetSymbolAddress((void**)&gp, g_p);
    cudaGetSymbolAddress((void**)&stats, g_stats);
    cudaGetSymbolAddress((void**)&part, g_part);

    dim3 gridA(NCHUNK, B);
    fused_kernel<<<gridA, 256>>>(query, key, value, gp, stats, part);
    merge_kernel<<<B, 256>>>(gp, stats, part, out, attn);
}

// round 14
// speedup vs baseline: 1.1173x; 1.1173x over previous
#include <cuda_runtime.h>
#include <math_constants.h>

// Problem: B=32, T=2048, D=512, fp32
//   energy[b,t]    = dot(key[b,t,:], query[b,:])
//   attention[b,t] = softmax_T(energy)[b,t]
//   out[b,d]       = sum_t attention[b,t] * value[b,t,d]
// d_out layout: out (32*512 floats) then attention (32*2048 floats)
//
// Split-softmax (exact): per 32-row chunk compute local m, p=exp(e-m), s=sum p,
// partial_out = sum p*V. Merge: M=max m, S=sum s*exp(m-M);
// attn = p*exp(m-M)/S, out = sum partial*exp(m-M)/S.

#define B 32
#define T 2048
#define D 512
#define CHUNK 32
#define NCHUNK (T / CHUNK)   // 64
#define MSPLIT 8             // merge blocks per batch

// Scratch (no allocations allowed in kernel_launch)
__device__ float g_p[B * T];                    // exp(e - m_chunk)
__device__ float g_stats[B * NCHUNK * 2];       // (m, s) per chunk
__device__ float g_part[B * NCHUNK * D];        // per-chunk partial out (4MB)

// ---------------------------------------------------------------------------
// Kernel A: fused QK + local softmax + weighted V accumulation per chunk.
// Grid (NCHUNK, B) = 2048 blocks x 256 threads.  (measured ~5.7 TB/s)
// ---------------------------------------------------------------------------
__global__ void __launch_bounds__(256) fused_kernel(
        const float* __restrict__ query,
        const float* __restrict__ key,
        const float* __restrict__ value,
        float* __restrict__ gp,
        float* __restrict__ stats,
        float* __restrict__ part) {
    int ts = blockIdx.x;        // chunk index 0..63
    int b  = blockIdx.y;        // batch
    int tid = threadIdx.x;      // 0..255
    int lane = tid & 31;
    int warp = tid >> 5;        // 0..7

    __shared__ float4 qs[D / 4];      // 2KB: q row for this batch
    __shared__ float es[CHUNK];       // raw energies
    __shared__ float ps[CHUNK];       // exp(e - m)
    __shared__ float4 vtmp[D / 4];    // half-combine buffer

    if (tid < D / 4)
        qs[tid] = ((const float4*)(query + (size_t)b * D))[tid];
    __syncthreads();

    int t0 = ts * CHUNK;

    // ---- QK phase: warp w -> local rows [4w, 4w+4), two 2-row iterations.
    // Front-batch 8 streaming k LDG.128 before any arithmetic; q from smem.
#pragma unroll
    for (int it = 0; it < 2; it++) {
        int r = warp * 4 + it * 2;
        const float4* k0 = (const float4*)(key + ((size_t)b * T + t0 + r) * D);

        float4 ka[4], kb[4];
#pragma unroll
        for (int i = 0; i < 4; i++) ka[i] = k0[lane + 32 * i];
#pragma unroll
        for (int i = 0; i < 4; i++) kb[i] = k0[128 + lane + 32 * i];

        float acc0 = 0.0f, acc1 = 0.0f;
#pragma unroll
        for (int i = 0; i < 4; i++) {
            float4 qv = qs[lane + 32 * i];
            acc0 += ka[i].x * qv.x + ka[i].y * qv.y +
                    ka[i].z * qv.z + ka[i].w * qv.w;
            acc1 += kb[i].x * qv.x + kb[i].y * qv.y +
                    kb[i].z * qv.z + kb[i].w * qv.w;
        }
#pragma unroll
        for (int off = 16; off; off >>= 1) {
            acc0 += __shfl_xor_sync(0xFFFFFFFFu, acc0, off);
            acc1 += __shfl_xor_sync(0xFFFFFFFFu, acc1, off);
        }
        if (lane == 0) {
            es[r]     = acc0;
            es[r + 1] = acc1;
        }
    }
    __syncthreads();

    // ---- Local softmax stats: warp 0 (32 values = CHUNK).
    if (warp == 0) {
        float e = es[lane];
        float m = e;
#pragma unroll
        for (int off = 16; off; off >>= 1)
            m = fmaxf(m, __shfl_xor_sync(0xFFFFFFFFu, m, off));
        float p = __expf(e - m);
        float s = p;
#pragma unroll
        for (int off = 16; off; off >>= 1)
            s += __shfl_xor_sync(0xFFFFFFFFu, s, off);
        ps[lane] = p;
        gp[(size_t)b * T + t0 + lane] = p;
        if (lane == 0) {
            stats[((size_t)b * NCHUNK + ts) * 2]     = m;
            stats[((size_t)b * NCHUNK + ts) * 2 + 1] = s;
        }
    }
    __syncthreads();

    // ---- V phase: thread owns float4 column c; halves h=0/1 cover 16 rows.
    int c = tid & 127;
    int h = tid >> 7;
    const float4* v0 = (const float4*)(value + ((size_t)b * T + t0 + h * 16) * D);
    float4 acc = make_float4(0.f, 0.f, 0.f, 0.f);
#pragma unroll 8
    for (int i = 0; i < 16; i++) {
        float a = ps[h * 16 + i];
        float4 vv = v0[(size_t)i * (D / 4) + c];
        acc.x += a * vv.x;
        acc.y += a * vv.y;
        acc.z += a * vv.z;
        acc.w += a * vv.w;
    }
    if (h == 1) vtmp[c] = acc;
    __syncthreads();
    if (h == 0) {
        float4 o = vtmp[c];
        acc.x += o.x; acc.y += o.y; acc.z += o.z; acc.w += o.w;
        ((float4*)part)[((size_t)b * NCHUNK + ts) * (D / 4) + c] = acc;
    }
}

// ---------------------------------------------------------------------------
// Kernel B: merge, parallelized. Grid (MSPLIT, B) = 256 blocks x 256 thr.
// Each block: recompute w[64] from 512B stats (L2-hot), scale 256 attn
// values, reduce 16 out float4-columns over 64 chunks.
// ---------------------------------------------------------------------------
__global__ void __launch_bounds__(256) merge_kernel(
        const float* __restrict__ gp,
        const float* __restrict__ stats,
        const float* __restrict__ part,
        float* __restrict__ out,
        float* __restrict__ attn) {
    int seg = blockIdx.x;       // 0..7
    int b = blockIdx.y;
    int tid = threadIdx.x;      // 0..255
    int lane = tid & 31;
    int warp = tid >> 5;

    __shared__ float w[NCHUNK];
    __shared__ float4 pbuf[16][17];   // [group][col], padded

    if (warp == 0) {
        const float* st = stats + (size_t)b * NCHUNK * 2;
        float m0 = st[lane * 2],        s0 = st[lane * 2 + 1];
        float m1 = st[(lane + 32) * 2], s1 = st[(lane + 32) * 2 + 1];
        float M = fmaxf(m0, m1);
#pragma unroll
        for (int off = 16; off; off >>= 1)
            M = fmaxf(M, __shfl_xor_sync(0xFFFFFFFFu, M, off));
        float e0 = __expf(m0 - M), e1 = __expf(m1 - M);
        float s = s0 * e0 + s1 * e1;
#pragma unroll
        for (int off = 16; off; off >>= 1)
            s += __shfl_xor_sync(0xFFFFFFFFu, s, off);
        float invS = 1.0f / s;
        w[lane]      = e0 * invS;
        w[lane + 32] = e1 * invS;
    }
    __syncthreads();

    // attention: this block handles t in [seg*256, seg*256+256)
    {
        int t = seg * 256 + tid;
        attn[(size_t)b * T + t] = gp[(size_t)b * T + t] * w[t >> 5];  // CHUNK=32
    }

    // out: 16 float4 columns; thread = (col c_l 0..15, chunk-group g 0..15)
    int c_l = tid & 15;
    int g = tid >> 4;
    int c = seg * 16 + c_l;
    const float4* pb = (const float4*)part + (size_t)b * NCHUNK * (D / 4);
    float4 acc = make_float4(0.f, 0.f, 0.f, 0.f);
#pragma unroll
    for (int i = 0; i < 4; i++) {
        int ts = g * 4 + i;
        float4 p = pb[(size_t)ts * (D / 4) + c];
        float ww = w[ts];
        acc.x += ww * p.x;
        acc.y += ww * p.y;
        acc.z += ww * p.z;
        acc.w += ww * p.w;
    }
    pbuf[g][c_l] = acc;
    __syncthreads();

    if (g == 0) {
        float4 s = pbuf[0][c_l];
#pragma unroll
        for (int gg = 1; gg < 16; gg++) {
            float4 p = pbuf[gg][c_l];
            s.x += p.x; s.y += p.y; s.z += p.z; s.w += p.w;
        }
        ((float4*)out)[(size_t)b * (D / 4) + c] = s;
    }
}

extern "C" void kernel_launch(void* const* d_in, const int* in_sizes, int n_in,
                              void* d_out, int out_size) {
    const float* query = (const float*)d_in[0];  // [B, D]
    const float* key   = (const float*)d_in[1];  // [B, T, D]
    const float* value = (const float*)d_in[2];  // [B, T, D]

    float* out  = (float*)d_out;            // [B, D]
    float* attn = (float*)d_out + B * D;    // [B, T]

    float *gp, *stats, *part;
    cudaGetSymbolAddress((void**)&gp, g_p);
    cudaGetSymbolAddress((void**)&stats, g_stats);
    cudaGetSymbolAddress((void**)&part, g_part);

    dim3 gridA(NCHUNK, B);
    fused_kernel<<<gridA, 256>>>(query, key, value, gp, stats, part);
    dim3 gridB(MSPLIT, B);
    merge_kernel<<<gridB, 256>>>(gp, stats, part, out, attn);
}